// round 15
// baseline (speedup 1.0000x reference)
#include <cuda_runtime.h>
#include <cuda_fp16.h>
#include <mma.h>

#define N_NODES 100000
#define N_EDGES 1600000
#define F 128
#define NB_SCAN 98            // ceil(100000/1024)
#define TB_F1 384             // fused1 block size (12 warps, 48 nodes/block)
#define NB_F1 2084            // ceil(100000/48)

#define NB_FILL   1563        // ceil(N_EDGES/4 / 256)
#define NB_TOHALF 6250        // N_NODES*16 / 256
#define NB_PREP   (NB_FILL + NB_TOHALF)   // 7813; fill blocks: b % 5 == 0

// smem layout (bytes) for k_fused1
#define SM_W1H  0             // __half [128][136] = 34816  (row-major [k][n])
#define SM_AT   34816         // __half [48][136]  = 13056  (row-major [node][k])
#define SM_H    47872         // float  [48][132]  = 25344
#define SM_B1   73216         // float  [128]      = 512
#define SM_W2   73728         // float  [256]      = 1024
#define SM_F1_TOTAL 74752

// ---------------- scratch (static __device__, no allocation) ----------------
__device__ int   g_deg_out_i[N_NODES];
__device__ int   g_deg_in_i[N_NODES];
__device__ float g_rs_out[N_NODES];
__device__ float g_rs_in[N_NODES];
__device__ int   g_rowp[N_NODES + 1];     // CSR row pointers (by dst)
__device__ int   g_cursor[N_NODES];       // fill cursors
__device__ int   g_csr[N_EDGES];          // src indices grouped by dst
__device__ int   g_bsum[NB_SCAN];
__device__ float g_y[(size_t)N_NODES * 2];
__device__ __align__(16) __half g_xh[(size_t)N_NODES * F];  // fp16(x * rs_out)
__device__ __align__(16) __half g_w1h[F * F];               // fp16(W1), [k][n]

// ---------------- zero counters + W1 -> fp16 ---------------------------------
__global__ void k_zero(const float* __restrict__ W1) {
    int i = blockIdx.x * blockDim.x + threadIdx.x;
    if (i < N_NODES) { g_deg_out_i[i] = 0; g_deg_in_i[i] = 0; }
    if (i < F * F / 2) {                       // 8192 float2 -> half2
        float2 v = ((const float2*)W1)[i];
        ((__half2*)g_w1h)[i] = __floats2half2_rn(v.x, v.y);
    }
}

// ---------------- degrees (int histogram, 4 edges/thread) --------------------
__global__ void k_deg(const int4* __restrict__ src4, const int4* __restrict__ dst4) {
    int i = blockIdx.x * blockDim.x + threadIdx.x;
    if (i < N_EDGES / 4) {
        int4 s = src4[i], d = dst4[i];
        atomicAdd(&g_deg_out_i[s.x], 1);
        atomicAdd(&g_deg_out_i[s.y], 1);
        atomicAdd(&g_deg_out_i[s.z], 1);
        atomicAdd(&g_deg_out_i[s.w], 1);
        atomicAdd(&g_deg_in_i[d.x], 1);
        atomicAdd(&g_deg_in_i[d.y], 1);
        atomicAdd(&g_deg_in_i[d.z], 1);
        atomicAdd(&g_deg_in_i[d.w], 1);
    }
}

// ---------------- block scan of deg_in (warp-shuffle) + rs -------------------
__global__ void k_scan_block() {
    __shared__ int wsum[32];
    int tid = threadIdx.x, lane = tid & 31, wid = tid >> 5;
    int gid = blockIdx.x * 1024 + tid;
    int v = (gid < N_NODES) ? g_deg_in_i[gid] : 0;
    int x = v;
    #pragma unroll
    for (int off = 1; off < 32; off <<= 1) {
        int t = __shfl_up_sync(0xffffffffu, x, off);
        if (lane >= off) x += t;
    }
    if (lane == 31) wsum[wid] = x;
    __syncthreads();
    if (wid == 0) {
        int s = wsum[lane];
        #pragma unroll
        for (int off = 1; off < 32; off <<= 1) {
            int t = __shfl_up_sync(0xffffffffu, s, off);
            if (lane >= off) s += t;
        }
        wsum[lane] = s;
    }
    __syncthreads();
    int inc = x + (wid ? wsum[wid - 1] : 0);
    if (gid < N_NODES) {
        g_rowp[gid + 1] = inc;                         // inclusive, pre-offset
        g_rs_in[gid]  = rsqrtf(fmaxf((float)v, 1.0f));
        g_rs_out[gid] = rsqrtf(fmaxf((float)g_deg_out_i[gid], 1.0f));
    }
    if (tid == 1023) g_bsum[blockIdx.x] = inc;
}

// ---------------- finalize scan: 391 light blocks, warp-reduced offset -------
// Block b covers gids [b*256, b*256+256) — all within 1024-segment b>>2,
// so the needed offset is sum(bsum[0 .. b>>2)).
__global__ void __launch_bounds__(256) k_scan_fin() {  // grid 391, block 256
    __shared__ int s_off;
    int tid = threadIdx.x;
    int seg = blockIdx.x >> 2;
    if (tid < 32) {
        int v = 0;
        for (int j = tid; j < seg; j += 32) v += g_bsum[j];
        #pragma unroll
        for (int off = 16; off; off >>= 1) v += __shfl_xor_sync(0xffffffffu, v, off);
        if (tid == 0) s_off = v;
    }
    __syncthreads();
    int off = s_off;
    int gid = blockIdx.x * 256 + tid;
    if (gid < N_NODES) {
        int val = g_rowp[gid + 1] + off;
        g_rowp[gid + 1] = val;
        if (gid + 1 < N_NODES) g_cursor[gid + 1] = val;
        if (gid == 0) { g_rowp[0] = 0; g_cursor[0] = 0; }
    }
}

// ---------------- fused prep: interleaved fill + x->fp16 ---------------------
// fill blocks: b % 5 == 0 (exactly NB_FILL of NB_PREP); tohalf: the rest.
// Interleaving keeps both workload types co-resident on every wave.
__global__ void __launch_bounds__(256) k_prep(const float4* __restrict__ x4,
                                              const int4* __restrict__ src4,
                                              const int4* __restrict__ dst4) {
    int b = blockIdx.x;
    if (b % 5 == 0) {                               // fill block, idx = b/5
        int i = (b / 5) * 256 + threadIdx.x;
        if (i < N_EDGES / 4) {
            int4 s = src4[i], d = dst4[i];
            int p0 = atomicAdd(&g_cursor[d.x], 1); g_csr[p0] = s.x;
            int p1 = atomicAdd(&g_cursor[d.y], 1); g_csr[p1] = s.y;
            int p2 = atomicAdd(&g_cursor[d.z], 1); g_csr[p2] = s.z;
            int p3 = atomicAdd(&g_cursor[d.w], 1); g_csr[p3] = s.w;
        }
    } else {                                        // tohalf block
        int tb = b - b / 5 - 1;                     // 0..NB_TOHALF-1
        int i = tb * 256 + threadIdx.x;             // < N_NODES*16 exactly
        int j0 = i * 2;
        float c = g_rs_out[j0 >> 5];
        float4 v0 = x4[j0], v1 = x4[j0 + 1];
        __half2 h0 = __floats2half2_rn(v0.x * c, v0.y * c);
        __half2 h1 = __floats2half2_rn(v0.z * c, v0.w * c);
        __half2 h2 = __floats2half2_rn(v1.x * c, v1.y * c);
        __half2 h3 = __floats2half2_rn(v1.z * c, v1.w * c);
        ((uint4*)g_xh)[i] = make_uint4(*(unsigned*)&h0, *(unsigned*)&h1,
                                       *(unsigned*)&h2, *(unsigned*)&h3);
    }
}

// ---------------- fused layer-1: gather + wmma W1 GEMM + relu + W2 -> y ------
__global__ void __launch_bounds__(TB_F1, 3) k_fused1(const float* __restrict__ b1,
                                                     const float* __restrict__ W2) {
    using namespace nvcuda;
    extern __shared__ char smraw[];
    __half* W1h = (__half*)(smraw + SM_W1H);   // [k=128][n=136 pad] row-major
    __half* At  = (__half*)(smraw + SM_AT);    // [node=48][k=136 pad] row-major
    float*  Hs  = (float*)(smraw + SM_H);      // [node=48][n=132 pad]
    float*  b1s = (float*)(smraw + SM_B1);     // [128]
    float*  W2s = (float*)(smraw + SM_W2);     // [256]

    int tid = threadIdx.x;
    // stage fp16 W1 from global (2048 uint4 = 16384 halves), keep [k][n] + pad
    for (int idx = tid; idx < 2048; idx += TB_F1) {
        int k = idx >> 4, n8 = idx & 15;       // 16 uint4 per 128-wide row
        *(uint4*)(W1h + k * 136 + n8 * 8) = ((const uint4*)g_w1h)[idx];
    }
    if (tid < 128) b1s[tid] = b1[tid];
    if (tid < 256) W2s[tid] = W2[tid];

    int warp = tid >> 5, lane = tid & 31;
    int i0 = blockIdx.x * 48 + warp * 4;

    const uint2* xh2 = (const uint2*)g_xh;     // 4 halves per lane per edge

    // --- gather: 4 nodes/warp, lane owns feats 4l..4l+3, dual fp32 chains ---
    #pragma unroll
    for (int m = 0; m < 4; m++) {
        int node = i0 + m;
        float4 accA = make_float4(0.f, 0.f, 0.f, 0.f);
        float4 accB = make_float4(0.f, 0.f, 0.f, 0.f);
        if (node < N_NODES) {
            int beg = __ldg(&g_rowp[node]), end = __ldg(&g_rowp[node + 1]);
            int e = beg;
            for (; e + 4 <= end; e += 4) {
                int s0 = __ldg(&g_csr[e]),     s1 = __ldg(&g_csr[e + 1]);
                int s2 = __ldg(&g_csr[e + 2]), s3 = __ldg(&g_csr[e + 3]);
                uint2 v0 = xh2[s0 * 32 + lane];
                uint2 v1 = xh2[s1 * 32 + lane];
                uint2 v2 = xh2[s2 * 32 + lane];
                uint2 v3 = xh2[s3 * 32 + lane];
                float2 f;
                f = __half22float2(*(__half2*)&v0.x); accA.x += f.x; accA.y += f.y;
                f = __half22float2(*(__half2*)&v0.y); accA.z += f.x; accA.w += f.y;
                f = __half22float2(*(__half2*)&v1.x); accB.x += f.x; accB.y += f.y;
                f = __half22float2(*(__half2*)&v1.y); accB.z += f.x; accB.w += f.y;
                f = __half22float2(*(__half2*)&v2.x); accA.x += f.x; accA.y += f.y;
                f = __half22float2(*(__half2*)&v2.y); accA.z += f.x; accA.w += f.y;
                f = __half22float2(*(__half2*)&v3.x); accB.x += f.x; accB.y += f.y;
                f = __half22float2(*(__half2*)&v3.y); accB.z += f.x; accB.w += f.y;
            }
            for (; e < end; ++e) {
                int s0 = __ldg(&g_csr[e]);
                uint2 v0 = xh2[s0 * 32 + lane];
                float2 f;
                f = __half22float2(*(__half2*)&v0.x); accA.x += f.x; accA.y += f.y;
                f = __half22float2(*(__half2*)&v0.y); accA.z += f.x; accA.w += f.y;
            }
            float ri = g_rs_in[node];
            accA.x = (accA.x + accB.x) * ri;
            accA.y = (accA.y + accB.y) * ri;
            accA.z = (accA.z + accB.z) * ri;
            accA.w = (accA.w + accB.w) * ri;
        }
        __half2 h01 = __floats2half2_rn(accA.x, accA.y);
        __half2 h23 = __floats2half2_rn(accA.z, accA.w);
        *(uint2*)(At + (warp * 4 + m) * 136 + 4 * lane) =
            make_uint2(*(unsigned*)&h01, *(unsigned*)&h23);
    }
    __syncthreads();   // A tile + W1h ready

    // --- wmma: H = A(48x128) @ W1(128x128), 24 tiles, 2 per warp ---
    {
        wmma::fragment<wmma::matrix_a, 16, 16, 16, __half, wmma::row_major> af;
        wmma::fragment<wmma::matrix_b, 16, 16, 16, __half, wmma::row_major> bf;
        wmma::fragment<wmma::accumulator, 16, 16, 16, float> cf;
        #pragma unroll
        for (int t = warp; t < 24; t += 12) {
            int mi = t >> 3, ni = t & 7;
            wmma::fill_fragment(cf, 0.0f);
            #pragma unroll
            for (int k0 = 0; k0 < 8; k0++) {
                wmma::load_matrix_sync(af, At + (mi * 16) * 136 + k0 * 16, 136);
                wmma::load_matrix_sync(bf, W1h + (k0 * 16) * 136 + ni * 16, 136);
                wmma::mma_sync(cf, af, bf, cf);
            }
            wmma::store_matrix_sync(Hs + (mi * 16) * 132 + ni * 16, cf, 132,
                                    wmma::mem_row_major);
        }
    }
    __syncthreads();   // H ready

    // --- epilogue: h = relu(H + b1); p = h @ W2; warp-reduce; *rs_out -> y ---
    float4 bb = ((const float4*)b1s)[lane];
    float2 w0 = ((float2*)W2s)[4 * lane + 0], w1 = ((float2*)W2s)[4 * lane + 1];
    float2 w2 = ((float2*)W2s)[4 * lane + 2], w3 = ((float2*)W2s)[4 * lane + 3];
    float p0[4], p1[4];
    #pragma unroll
    for (int m = 0; m < 4; m++) {
        float4 h = *(float4*)(Hs + (warp * 4 + m) * 132 + 4 * lane);
        float h0 = fmaxf(h.x + bb.x, 0.f), h1 = fmaxf(h.y + bb.y, 0.f);
        float h2 = fmaxf(h.z + bb.z, 0.f), h3 = fmaxf(h.w + bb.w, 0.f);
        p0[m] = h0 * w0.x + h1 * w1.x + h2 * w2.x + h3 * w3.x;
        p1[m] = h0 * w0.y + h1 * w1.y + h2 * w2.y + h3 * w3.y;
    }
    #pragma unroll
    for (int off = 16; off; off >>= 1) {
        #pragma unroll
        for (int m = 0; m < 4; m++) {
            p0[m] += __shfl_xor_sync(0xffffffffu, p0[m], off);
            p1[m] += __shfl_xor_sync(0xffffffffu, p1[m], off);
        }
    }
    if (lane == 0) {
        float2* y2 = (float2*)g_y;
        #pragma unroll
        for (int m = 0; m < 4; m++) {
            int node = i0 + m;
            if (node < N_NODES) {
                float ro = g_rs_out[node];
                y2[node] = make_float2(p0[m] * ro, p1[m] * ro);
            }
        }
    }
}

// ---------------- layer-2: CSR gather of y + finalize (unroll-4) -------------
__global__ void k_out(float* __restrict__ out, const float* __restrict__ b2) {
    int i = blockIdx.x * blockDim.x + threadIdx.x;
    if (i >= N_NODES) return;
    int beg = __ldg(&g_rowp[i]), end = __ldg(&g_rowp[i + 1]);
    const float2* y2 = (const float2*)g_y;
    float s0 = 0.f, s1 = 0.f, t0 = 0.f, t1 = 0.f;
    int e = beg;
    for (; e + 4 <= end; e += 4) {
        int a = __ldg(&g_csr[e]),     b = __ldg(&g_csr[e + 1]);
        int c = __ldg(&g_csr[e + 2]), d = __ldg(&g_csr[e + 3]);
        float2 va = y2[a], vb = y2[b], vc = y2[c], vd = y2[d];
        s0 += va.x + vb.x;  s1 += va.y + vb.y;
        t0 += vc.x + vd.x;  t1 += vc.y + vd.y;
    }
    for (; e < end; ++e) {
        float2 va = y2[__ldg(&g_csr[e])];
        s0 += va.x; s1 += va.y;
    }
    s0 += t0; s1 += t1;
    float ri = g_rs_in[i];
    ((float2*)out)[i] = make_float2(s0 * ri + __ldg(&b2[0]),
                                    s1 * ri + __ldg(&b2[1]));
}

// ---------------- launch ------------------------------------------------------
extern "C" void kernel_launch(void* const* d_in, const int* in_sizes, int n_in,
                              void* d_out, int out_size) {
    const float* in_feat = (const float*)d_in[0];
    const int*   src     = (const int*)d_in[1];
    const int*   dst     = (const int*)d_in[2];
    const float* W1      = (const float*)d_in[3];
    const float* b1      = (const float*)d_in[4];
    const float* W2      = (const float*)d_in[5];
    const float* b2      = (const float*)d_in[6];
    float*       out     = (float*)d_out;

    const int T = 256;
    cudaFuncSetAttribute(k_fused1, cudaFuncAttributeMaxDynamicSharedMemorySize, SM_F1_TOTAL);

    k_zero<<<(N_NODES + T - 1) / T, T>>>(W1);
    k_deg<<<(N_EDGES / 4 + T - 1) / T, T>>>((const int4*)src, (const int4*)dst);
    k_scan_block<<<NB_SCAN, 1024>>>();
    k_scan_fin<<<391, 256>>>();
    k_prep<<<NB_PREP, T>>>((const float4*)in_feat, (const int4*)src, (const int4*)dst);
    k_fused1<<<NB_F1, TB_F1, SM_F1_TOTAL>>>(b1, W2);
    k_out<<<(N_NODES + T - 1) / T, T>>>(out, b2);
}

// round 17
// speedup vs baseline: 1.0410x; 1.0410x over previous
#include <cuda_runtime.h>
#include <cuda_fp16.h>
#include <mma.h>

#define N_NODES 100000
#define N_EDGES 1600000
#define F 128
#define NB_SCAN 98            // ceil(100000/1024)
#define TB_F1 384             // fused1 block size (12 warps, 48 nodes/tile)
#define N_TILES 2084          // ceil(100000/48)
#define NB_F1 444             // persistent: 148 SMs * 3 CTAs

#define NB_FILL   1563        // ceil(N_EDGES/4 / 256)
#define NB_TOHALF 6250        // N_NODES*16 / 256
#define NB_PREP   (NB_FILL + NB_TOHALF)

// smem layout (bytes) for k_fused1
#define SM_W1H  0             // __half [128][136] = 34816  (row-major [k][n])
#define SM_AT   34816         // __half [48][136]  = 13056  (row-major [node][k])
#define SM_H    47872         // float  [48][132]  = 25344
#define SM_B1   73216         // float  [128]      = 512
#define SM_W2   73728         // float  [256]      = 1024
#define SM_F1_TOTAL 74752

// ---------------- scratch (static __device__, no allocation) ----------------
__device__ int   g_deg_out_i[N_NODES];
__device__ int   g_deg_in_i[N_NODES];
__device__ float g_rs_out[N_NODES];
__device__ float g_rs_in[N_NODES];
__device__ int   g_rowp[N_NODES + 1];     // CSR row pointers (by dst)
__device__ int   g_cursor[N_NODES];       // fill cursors
__device__ int   g_csr[N_EDGES];          // src indices grouped by dst
__device__ int   g_bsum[NB_SCAN];
__device__ float g_y[(size_t)N_NODES * 2];
__device__ __align__(16) __half g_xh[(size_t)N_NODES * F];  // fp16(x * rs_out)
__device__ __align__(16) __half g_w1h[F * F];               // fp16(W1), [k][n]

// ---------------- zero counters + W1 -> fp16 ---------------------------------
__global__ void k_zero(const float* __restrict__ W1) {
    int i = blockIdx.x * blockDim.x + threadIdx.x;
    if (i < N_NODES) { g_deg_out_i[i] = 0; g_deg_in_i[i] = 0; }
    if (i < F * F / 2) {                       // 8192 float2 -> half2
        float2 v = ((const float2*)W1)[i];
        ((__half2*)g_w1h)[i] = __floats2half2_rn(v.x, v.y);
    }
}

// ---------------- degrees (int histogram, 4 edges/thread) --------------------
__global__ void k_deg(const int4* __restrict__ src4, const int4* __restrict__ dst4) {
    int i = blockIdx.x * blockDim.x + threadIdx.x;
    if (i < N_EDGES / 4) {
        int4 s = src4[i], d = dst4[i];
        atomicAdd(&g_deg_out_i[s.x], 1);
        atomicAdd(&g_deg_out_i[s.y], 1);
        atomicAdd(&g_deg_out_i[s.z], 1);
        atomicAdd(&g_deg_out_i[s.w], 1);
        atomicAdd(&g_deg_in_i[d.x], 1);
        atomicAdd(&g_deg_in_i[d.y], 1);
        atomicAdd(&g_deg_in_i[d.z], 1);
        atomicAdd(&g_deg_in_i[d.w], 1);
    }
}

// ---------------- block scan of deg_in (warp-shuffle) + rs -------------------
__global__ void k_scan_block() {
    __shared__ int wsum[32];
    int tid = threadIdx.x, lane = tid & 31, wid = tid >> 5;
    int gid = blockIdx.x * 1024 + tid;
    int v = (gid < N_NODES) ? g_deg_in_i[gid] : 0;
    int x = v;
    #pragma unroll
    for (int off = 1; off < 32; off <<= 1) {
        int t = __shfl_up_sync(0xffffffffu, x, off);
        if (lane >= off) x += t;
    }
    if (lane == 31) wsum[wid] = x;
    __syncthreads();
    if (wid == 0) {
        int s = wsum[lane];
        #pragma unroll
        for (int off = 1; off < 32; off <<= 1) {
            int t = __shfl_up_sync(0xffffffffu, s, off);
            if (lane >= off) s += t;
        }
        wsum[lane] = s;
    }
    __syncthreads();
    int inc = x + (wid ? wsum[wid - 1] : 0);
    if (gid < N_NODES) {
        g_rowp[gid + 1] = inc;                         // inclusive, pre-offset
        g_rs_in[gid]  = rsqrtf(fmaxf((float)v, 1.0f));
        g_rs_out[gid] = rsqrtf(fmaxf((float)g_deg_out_i[gid], 1.0f));
    }
    if (tid == 1023) g_bsum[blockIdx.x] = inc;
}

// ---------------- finalize scan: per-block offset reduce + add-back ----------
__global__ void k_scan_fin() {                         // grid NB_SCAN, block 1024
    __shared__ int wred[32];
    __shared__ int s_off;
    int tid = threadIdx.x, lane = tid & 31, wid = tid >> 5;
    int bid = blockIdx.x;
    int v = (tid < bid) ? g_bsum[tid] : 0;             // bid <= 97 < 1024
    #pragma unroll
    for (int off = 16; off; off >>= 1) v += __shfl_xor_sync(0xffffffffu, v, off);
    if (lane == 0) wred[wid] = v;
    __syncthreads();
    if (wid == 0) {
        int t = wred[lane];
        #pragma unroll
        for (int off = 16; off; off >>= 1) t += __shfl_xor_sync(0xffffffffu, t, off);
        if (lane == 0) s_off = t;
    }
    __syncthreads();
    int off = s_off;
    int gid = bid * 1024 + tid;
    if (gid < N_NODES) {
        int val = g_rowp[gid + 1] + off;
        g_rowp[gid + 1] = val;
        if (gid + 1 < N_NODES) g_cursor[gid + 1] = val;
        if (gid == 0) { g_rowp[0] = 0; g_cursor[0] = 0; }
    }
}

// ---------------- fused prep: CSR fill (blocks [0,NB_FILL)) +  ---------------
// ----------------             x->fp16 (blocks [NB_FILL,NB_PREP)) -------------
__global__ void __launch_bounds__(256) k_prep(const float4* __restrict__ x4,
                                              const int4* __restrict__ src4,
                                              const int4* __restrict__ dst4) {
    int b = blockIdx.x;
    if (b < NB_FILL) {
        int i = b * 256 + threadIdx.x;
        if (i < N_EDGES / 4) {
            int4 s = src4[i], d = dst4[i];
            int p0 = atomicAdd(&g_cursor[d.x], 1); g_csr[p0] = s.x;
            int p1 = atomicAdd(&g_cursor[d.y], 1); g_csr[p1] = s.y;
            int p2 = atomicAdd(&g_cursor[d.z], 1); g_csr[p2] = s.z;
            int p3 = atomicAdd(&g_cursor[d.w], 1); g_csr[p3] = s.w;
        }
    } else {
        int i = (b - NB_FILL) * 256 + threadIdx.x;   // < N_NODES*16 exactly
        int j0 = i * 2;
        float c = g_rs_out[j0 >> 5];
        float4 v0 = x4[j0], v1 = x4[j0 + 1];
        __half2 h0 = __floats2half2_rn(v0.x * c, v0.y * c);
        __half2 h1 = __floats2half2_rn(v0.z * c, v0.w * c);
        __half2 h2 = __floats2half2_rn(v1.x * c, v1.y * c);
        __half2 h3 = __floats2half2_rn(v1.z * c, v1.w * c);
        ((uint4*)g_xh)[i] = make_uint4(*(unsigned*)&h0, *(unsigned*)&h1,
                                       *(unsigned*)&h2, *(unsigned*)&h3);
    }
}

// ---------------- fused layer-1 (PERSISTENT): gather + wmma + epilogue -------
// 444 blocks (1 wave at occ 3); each loops over tiles, staging W1/b1/W2 ONCE.
__global__ void __launch_bounds__(TB_F1, 3) k_fused1(const float* __restrict__ b1,
                                                     const float* __restrict__ W2) {
    using namespace nvcuda;
    extern __shared__ char smraw[];
    __half* W1h = (__half*)(smraw + SM_W1H);   // [k=128][n=136 pad] row-major
    __half* At  = (__half*)(smraw + SM_AT);    // [node=48][k=136 pad] row-major
    float*  Hs  = (float*)(smraw + SM_H);      // [node=48][n=132 pad]
    float*  b1s = (float*)(smraw + SM_B1);     // [128]
    float*  W2s = (float*)(smraw + SM_W2);     // [256]

    int tid = threadIdx.x;
    // stage fp16 W1 from global once per block (2048 uint4), keep [k][n] + pad
    for (int idx = tid; idx < 2048; idx += TB_F1) {
        int k = idx >> 4, n8 = idx & 15;       // 16 uint4 per 128-wide row
        *(uint4*)(W1h + k * 136 + n8 * 8) = ((const uint4*)g_w1h)[idx];
    }
    if (tid < 128) b1s[tid] = b1[tid];
    if (tid < 256) W2s[tid] = W2[tid];

    int warp = tid >> 5, lane = tid & 31;
    const uint2* xh2 = (const uint2*)g_xh;     // 4 halves per lane per edge

    for (int tile = blockIdx.x; tile < N_TILES; tile += NB_F1) {
        int i0 = tile * 48 + warp * 4;

        // --- gather: 4 nodes/warp, lane owns feats 4l..4l+3, dual chains ---
        #pragma unroll
        for (int m = 0; m < 4; m++) {
            int node = i0 + m;
            float4 accA = make_float4(0.f, 0.f, 0.f, 0.f);
            float4 accB = make_float4(0.f, 0.f, 0.f, 0.f);
            if (node < N_NODES) {
                int beg = __ldg(&g_rowp[node]), end = __ldg(&g_rowp[node + 1]);
                int e = beg;
                for (; e + 4 <= end; e += 4) {
                    int s0 = __ldg(&g_csr[e]),     s1 = __ldg(&g_csr[e + 1]);
                    int s2 = __ldg(&g_csr[e + 2]), s3 = __ldg(&g_csr[e + 3]);
                    uint2 v0 = xh2[s0 * 32 + lane];
                    uint2 v1 = xh2[s1 * 32 + lane];
                    uint2 v2 = xh2[s2 * 32 + lane];
                    uint2 v3 = xh2[s3 * 32 + lane];
                    float2 f;
                    f = __half22float2(*(__half2*)&v0.x); accA.x += f.x; accA.y += f.y;
                    f = __half22float2(*(__half2*)&v0.y); accA.z += f.x; accA.w += f.y;
                    f = __half22float2(*(__half2*)&v1.x); accB.x += f.x; accB.y += f.y;
                    f = __half22float2(*(__half2*)&v1.y); accB.z += f.x; accB.w += f.y;
                    f = __half22float2(*(__half2*)&v2.x); accA.x += f.x; accA.y += f.y;
                    f = __half22float2(*(__half2*)&v2.y); accA.z += f.x; accA.w += f.y;
                    f = __half22float2(*(__half2*)&v3.x); accB.x += f.x; accB.y += f.y;
                    f = __half22float2(*(__half2*)&v3.y); accB.z += f.x; accB.w += f.y;
                }
                for (; e < end; ++e) {
                    int s0 = __ldg(&g_csr[e]);
                    uint2 v0 = xh2[s0 * 32 + lane];
                    float2 f;
                    f = __half22float2(*(__half2*)&v0.x); accA.x += f.x; accA.y += f.y;
                    f = __half22float2(*(__half2*)&v0.y); accA.z += f.x; accA.w += f.y;
                }
                float ri = g_rs_in[node];
                accA.x = (accA.x + accB.x) * ri;
                accA.y = (accA.y + accB.y) * ri;
                accA.z = (accA.z + accB.z) * ri;
                accA.w = (accA.w + accB.w) * ri;
            }
            __half2 h01 = __floats2half2_rn(accA.x, accA.y);
            __half2 h23 = __floats2half2_rn(accA.z, accA.w);
            *(uint2*)(At + (warp * 4 + m) * 136 + 4 * lane) =
                make_uint2(*(unsigned*)&h01, *(unsigned*)&h23);
        }
        __syncthreads();   // A tile (+ W1h on first iter) ready

        // --- wmma: H = A(48x128) @ W1(128x128), 24 tiles, 2 per warp ---
        {
            wmma::fragment<wmma::matrix_a, 16, 16, 16, __half, wmma::row_major> af;
            wmma::fragment<wmma::matrix_b, 16, 16, 16, __half, wmma::row_major> bf;
            wmma::fragment<wmma::accumulator, 16, 16, 16, float> cf;
            #pragma unroll
            for (int t = warp; t < 24; t += 12) {
                int mi = t >> 3, ni = t & 7;
                wmma::fill_fragment(cf, 0.0f);
                #pragma unroll
                for (int k0 = 0; k0 < 8; k0++) {
                    wmma::load_matrix_sync(af, At + (mi * 16) * 136 + k0 * 16, 136);
                    wmma::load_matrix_sync(bf, W1h + (k0 * 16) * 136 + ni * 16, 136);
                    wmma::mma_sync(cf, af, bf, cf);
                }
                wmma::store_matrix_sync(Hs + (mi * 16) * 132 + ni * 16, cf, 132,
                                        wmma::mem_row_major);
            }
        }
        __syncthreads();   // H ready (also protects At reuse next iteration)

        // --- epilogue: h = relu(H + b1); p = h @ W2; reduce; *rs_out -> y ---
        float4 bv = ((const float4*)b1s)[lane];
        float2 w0 = ((float2*)W2s)[4 * lane + 0], w1 = ((float2*)W2s)[4 * lane + 1];
        float2 w2 = ((float2*)W2s)[4 * lane + 2], w3 = ((float2*)W2s)[4 * lane + 3];
        float p0[4], p1[4];
        #pragma unroll
        for (int m = 0; m < 4; m++) {
            float4 h = *(float4*)(Hs + (warp * 4 + m) * 132 + 4 * lane);
            float h0 = fmaxf(h.x + bv.x, 0.f), h1 = fmaxf(h.y + bv.y, 0.f);
            float h2 = fmaxf(h.z + bv.z, 0.f), h3 = fmaxf(h.w + bv.w, 0.f);
            p0[m] = h0 * w0.x + h1 * w1.x + h2 * w2.x + h3 * w3.x;
            p1[m] = h0 * w0.y + h1 * w1.y + h2 * w2.y + h3 * w3.y;
        }
        #pragma unroll
        for (int off = 16; off; off >>= 1) {
            #pragma unroll
            for (int m = 0; m < 4; m++) {
                p0[m] += __shfl_xor_sync(0xffffffffu, p0[m], off);
                p1[m] += __shfl_xor_sync(0xffffffffu, p1[m], off);
            }
        }
        if (lane == 0) {
            float2* y2 = (float2*)g_y;
            #pragma unroll
            for (int m = 0; m < 4; m++) {
                int node = i0 + m;
                if (node < N_NODES) {
                    float ro = g_rs_out[node];
                    y2[node] = make_float2(p0[m] * ro, p1[m] * ro);
                }
            }
        }
        __syncthreads();   // Hs safe to overwrite next iteration
    }
}

// ---------------- layer-2: CSR gather of y + finalize (unroll-4) -------------
__global__ void k_out(float* __restrict__ out, const float* __restrict__ b2) {
    int i = blockIdx.x * blockDim.x + threadIdx.x;
    if (i >= N_NODES) return;
    int beg = __ldg(&g_rowp[i]), end = __ldg(&g_rowp[i + 1]);
    const float2* y2 = (const float2*)g_y;
    float s0 = 0.f, s1 = 0.f, t0 = 0.f, t1 = 0.f;
    int e = beg;
    for (; e + 4 <= end; e += 4) {
        int a = __ldg(&g_csr[e]),     b = __ldg(&g_csr[e + 1]);
        int c = __ldg(&g_csr[e + 2]), d = __ldg(&g_csr[e + 3]);
        float2 va = y2[a], vb = y2[b], vc = y2[c], vd = y2[d];
        s0 += va.x + vb.x;  s1 += va.y + vb.y;
        t0 += vc.x + vd.x;  t1 += vc.y + vd.y;
    }
    for (; e < end; ++e) {
        float2 va = y2[__ldg(&g_csr[e])];
        s0 += va.x; s1 += va.y;
    }
    s0 += t0; s1 += t1;
    float ri = g_rs_in[i];
    ((float2*)out)[i] = make_float2(s0 * ri + __ldg(&b2[0]),
                                    s1 * ri + __ldg(&b2[1]));
}

// ---------------- launch ------------------------------------------------------
extern "C" void kernel_launch(void* const* d_in, const int* in_sizes, int n_in,
                              void* d_out, int out_size) {
    const float* in_feat = (const float*)d_in[0];
    const int*   src     = (const int*)d_in[1];
    const int*   dst     = (const int*)d_in[2];
    const float* W1      = (const float*)d_in[3];
    const float* b1      = (const float*)d_in[4];
    const float* W2      = (const float*)d_in[5];
    const float* b2      = (const float*)d_in[6];
    float*       out     = (float*)d_out;

    const int T = 256;
    cudaFuncSetAttribute(k_fused1, cudaFuncAttributeMaxDynamicSharedMemorySize, SM_F1_TOTAL);

    k_zero<<<(N_NODES + T - 1) / T, T>>>(W1);
    k_deg<<<(N_EDGES / 4 + T - 1) / T, T>>>((const int4*)src, (const int4*)dst);
    k_scan_block<<<NB_SCAN, 1024>>>();
    k_scan_fin<<<NB_SCAN, 1024>>>();
    k_prep<<<NB_PREP, T>>>((const float4*)in_feat, (const int4*)src, (const int4*)dst);
    k_fused1<<<NB_F1, TB_F1, SM_F1_TOTAL>>>(b1, W2);
    k_out<<<(N_NODES + T - 1) / T, T>>>(out, b2);
}